// round 5
// baseline (speedup 1.0000x reference)
#include <cuda_runtime.h>
#include <math.h>

#define BB 2048
#define LL 1024
#define HH 64
#define VV 64
#define TT 16          // chunk length
#define WPB 2          // warps per block

// ---------------- precomputed tables ----------------
__device__ float d_K[HH * HH];
__device__ float d_g[HH];
__device__ float d_Gn[HH * HH];    // Gn[v][j] = -a_v * (k_v . k_j)
__device__ float d_r[HH];          // r_v = ||k_v||^2 + 1e-6
__device__ float d_Y[HH * HH];
__device__ float d_Z[HH * HH];
__device__ float d_bias2[HH];

// ---------------- precompute A ----------------
__global__ void __launch_bounds__(128) prekA(
    const float* __restrict__ embed_W, const float* __restrict__ ff_w1, const float* __restrict__ ff_b1,
    const float* __restrict__ ff_w2,   const float* __restrict__ ff_b2, const float* __restrict__ ln_g,
    const float* __restrict__ ln_b,    const float* __restrict__ gate_w1, const float* __restrict__ gate_b1,
    const float* __restrict__ gate_w2, const float* __restrict__ gate_b2)
{
    int v = blockIdx.x;
    int tid = threadIdx.x;
    __shared__ float se[HH];
    __shared__ float sz[2 * HH];
    __shared__ float sk[HH];
    __shared__ float sh[16];
    __shared__ float sred[4];

    if (tid < HH) se[tid] = embed_W[v * HH + tid];
    __syncthreads();

    {
        float z = ff_b1[tid];
        #pragma unroll 8
        for (int i = 0; i < HH; i++) z = fmaf(se[i], ff_w1[i * (2 * HH) + tid], z);
        sz[tid] = fmaxf(z, 0.0f);
    }
    __syncthreads();

    if (tid < HH) {
        float ff = ff_b2[tid];
        #pragma unroll 8
        for (int j = 0; j < 2 * HH; j++) ff = fmaf(sz[j], ff_w2[j * HH + tid], ff);
        float x = se[tid] + ff;

        float s = x;
        #pragma unroll
        for (int o = 16; o > 0; o >>= 1) s += __shfl_xor_sync(0xffffffffu, s, o);
        if ((tid & 31) == 0) sred[tid >> 5] = s;
        __syncwarp();
        __syncthreads();
        float mu = (sred[0] + sred[1]) * (1.0f / HH);

        float d = x - mu;
        float sv = d * d;
        #pragma unroll
        for (int o = 16; o > 0; o >>= 1) sv += __shfl_xor_sync(0xffffffffu, sv, o);
        if ((tid & 31) == 0) sred[2 + (tid >> 5)] = sv;
        __syncwarp();
        __syncthreads();
        float var = (sred[2] + sred[3]) * (1.0f / HH);
        float inv = rsqrtf(var + 1e-5f);
        float k = d * inv * ln_g[tid] + ln_b[tid];
        sk[tid] = k;
        d_K[v * HH + tid] = k;
    }
    __syncthreads();

    if (tid < 16) {
        float hj = gate_b1[tid];
        #pragma unroll 8
        for (int i = 0; i < HH; i++) hj = fmaf(sk[i], gate_w1[i * 16 + tid], hj);
        sh[tid] = fmaxf(hj, 0.0f);
    }
    __syncthreads();
    if (tid == 0) {
        float gz = gate_b2[0];
        #pragma unroll
        for (int j = 0; j < 16; j++) gz = fmaf(sh[j], gate_w2[j], gz);
        d_g[v] = 1.0f / (1.0f + expf(-gz));
    }
}

// ---------------- precompute B ----------------
__global__ void __launch_bounds__(64) prekB(
    const float* __restrict__ read_w, const float* __restrict__ read_b,
    const float* __restrict__ out_w,  const float* __restrict__ out_b)
{
    int v = blockIdx.x;
    int u = threadIdx.x;
    __shared__ float skv[HH];
    __shared__ float sdiag;

    skv[u] = d_K[v * HH + u];
    __syncthreads();

    float s = 0.0f;
    #pragma unroll 8
    for (int i = 0; i < HH; i++) s = fmaf(skv[i], d_K[u * HH + i], s);
    if (u == v) sdiag = s;
    __syncthreads();

    float denom = sdiag + 1e-6f;
    float a = d_g[v] / denom;
    d_Gn[v * HH + u] = -a * s;
    if (u == v) d_r[v] = denom;

    float y = 0.0f;
    #pragma unroll 8
    for (int m = 0; m < HH; m++) y = fmaf(read_w[v * HH + m], out_w[m * HH + u], y);
    d_Y[v * HH + u] = y;

    if (v == 0) {
        float b = out_b[u];
        #pragma unroll 8
        for (int m = 0; m < HH; m++) b = fmaf(read_b[m], out_w[m * HH + u], b);
        d_bias2[u] = b;
    }
}

// ---------------- precompute C ----------------
__global__ void __launch_bounds__(64) prekC()
{
    int v = blockIdx.x;
    int n = threadIdx.x;
    __shared__ float skv[HH];
    skv[n] = d_K[v * HH + n];
    __syncthreads();
    float s = 0.0f;
    #pragma unroll 8
    for (int h = 0; h < HH; h++) s = fmaf(skv[h], d_Y[h * HH + n], s);
    d_Z[v * HH + n] = s;
}

// ---------------- packed dual-fp32 helpers ----------------
__device__ __forceinline__ unsigned long long fma_f32x2(unsigned long long a, unsigned long long b,
                                                        unsigned long long c) {
    unsigned long long d;
    asm("fma.rn.f32x2 %0, %1, %2, %3;" : "=l"(d) : "l"(a), "l"(b), "l"(c));
    return d;
}
__device__ __forceinline__ unsigned long long bcast2(float x) {
    unsigned long long r;
    unsigned int u = __float_as_uint(x);
    asm("mov.b64 %0, {%1, %2};" : "=l"(r) : "r"(u), "r"(u));
    return r;
}
__device__ __forceinline__ unsigned long long pack2(float x, float y) {
    unsigned long long r;
    asm("mov.b64 %0, {%1, %2};" : "=l"(r) : "f"(x), "f"(y));
    return r;
}
__device__ __forceinline__ void unpack2(unsigned long long v, float& x, float& y) {
    asm("mov.b64 {%0, %1}, %2;" : "=f"(x), "=f"(y) : "l"(v));
}

// ---------------- scan: chunked delta rule, one warp per batch ----------------
__global__ void __launch_bounds__(WPB * 32) scan_kernel(const int* __restrict__ seq, float* __restrict__ out)
{
    __shared__ float sGn[HH * HH];
    __shared__ float sr[HH];
    __shared__ __align__(16) float sS[WPB][TT][HH];   // per-warp s_t rows
    __shared__ float sC[WPB][TT][TT];                  // per-warp triangular coeffs
    __shared__ int   stok[WPB][TT];

    int tid = threadIdx.x;
    #pragma unroll 1
    for (int i = tid; i < HH * HH; i += WPB * 32) sGn[i] = d_Gn[i];
    if (tid < HH && tid < WPB * 32) sr[tid] = d_r[tid];
    // (WPB*32 == 64 == HH so all r loaded)
    __syncthreads();

    int w = tid >> 5;
    int lane = tid & 31;
    int b = blockIdx.x * WPB + w;
    const int* seqb = seq + (long)b * LL;
    float* Sm = &sS[w][0][0];
    float* Cm = &sC[w][0][0];
    int*   tok = stok[w];

    // Lane j owns columns j (cA) and j+32 (cB); u64 packs rows (2i, 2i+1).
    unsigned long long cA[32], cB[32];
    #pragma unroll
    for (int i = 0; i < 32; i++) { cA[i] = 0ull; cB[i] = 0ull; }

    const int nsteps = LL - 1;   // 1023
    #pragma unroll 1
    for (int c0 = 0; c0 < nsteps; c0 += TT) {
        int T = nsteps - c0; if (T > TT) T = TT;

        if (lane < T) tok[lane] = seqb[c0 + lane];
        __syncwarp();

        // ---- phase 1: dump needed columns of P0 into Sm rows (w_t), parallel owners ----
        #pragma unroll 1
        for (int t = 0; t < T; t++) {
            int v = tok[t];
            if (lane == (v & 31)) {
                float* row = Sm + t * HH;
                if (v & 32) {
                    #pragma unroll
                    for (int p = 0; p < 32; p += 2) {
                        ulonglong2 t2; t2.x = cB[p]; t2.y = cB[p + 1];
                        *reinterpret_cast<ulonglong2*>(row + 2 * p) = t2;
                    }
                } else {
                    #pragma unroll
                    for (int p = 0; p < 32; p += 2) {
                        ulonglong2 t2; t2.x = cA[p]; t2.y = cA[p + 1];
                        *reinterpret_cast<ulonglong2*>(row + 2 * p) = t2;
                    }
                }
                row[v] -= sr[v];
            }
        }

        // ---- build C[t][u] = Gn[v_u][v_t] (u < t) ----
        #pragma unroll 1
        for (int t = 1; t < T; t++) {
            if (lane < t) Cm[t * TT + lane] = sGn[tok[lane] * HH + tok[t]];
        }
        __syncwarp();

        // ---- phase 2: forward substitution, component-parallel (no cross-lane comm) ----
        {
            unsigned long long sreg[TT];
            #pragma unroll
            for (int t = 0; t < TT; t++) {
                if (t < T) {
                    float x1 = Sm[t * HH + lane];
                    float x2 = Sm[t * HH + 32 + lane];
                    unsigned long long acc = pack2(x1, x2);
                    const float* crow = Cm + t * TT;
                    #pragma unroll
                    for (int u = 0; u < t; u++)
                        acc = fma_f32x2(bcast2(crow[u]), sreg[u], acc);
                    sreg[t] = acc;
                    float y1, y2; unpack2(acc, y1, y2);
                    Sm[t * HH + lane] = y1;
                    Sm[t * HH + 32 + lane] = y2;
                }
            }
        }
        __syncwarp();

        // ---- phase 3: P += sum_u s_u * gn_u^T  (branch/sync-free rank-T update) ----
        #pragma unroll 2
        for (int u = 0; u < T; u++) {
            int v = tok[u];
            unsigned long long cp1 = bcast2(sGn[v * HH + lane]);
            unsigned long long cp2 = bcast2(sGn[v * HH + 32 + lane]);
            const ulonglong2* s2 = reinterpret_cast<const ulonglong2*>(Sm + u * HH);
            #pragma unroll
            for (int p = 0; p < 16; p++) {
                ulonglong2 sv = s2[p];
                cA[2 * p]     = fma_f32x2(cp1, sv.x, cA[2 * p]);
                cA[2 * p + 1] = fma_f32x2(cp1, sv.y, cA[2 * p + 1]);
                cB[2 * p]     = fma_f32x2(cp2, sv.x, cB[2 * p]);
                cB[2 * p + 1] = fma_f32x2(cp2, sv.y, cB[2 * p + 1]);
            }
        }
        __syncwarp();   // before next chunk's phase-1 overwrites Sm
    }

    // ---- final readout: logits = P[:,v_q]^T Z + bias2 ----
    int vq = seqb[LL - 1];
    float* sb = Sm;
    if (lane == (vq & 31)) {
        if (vq & 32) {
            #pragma unroll
            for (int p = 0; p < 32; p += 2) {
                ulonglong2 t2; t2.x = cB[p]; t2.y = cB[p + 1];
                *reinterpret_cast<ulonglong2*>(sb + 2 * p) = t2;
            }
        } else {
            #pragma unroll
            for (int p = 0; p < 32; p += 2) {
                ulonglong2 t2; t2.x = cA[p]; t2.y = cA[p + 1];
                *reinterpret_cast<ulonglong2*>(sb + 2 * p) = t2;
            }
        }
    }
    __syncwarp();

    float acc1 = d_bias2[lane];
    float acc2 = d_bias2[lane + 32];
    #pragma unroll 8
    for (int i = 0; i < HH; i++) {
        float pi = sb[i];
        acc1 = fmaf(pi, d_Z[i * HH + lane], acc1);
        acc2 = fmaf(pi, d_Z[i * HH + 32 + lane], acc2);
    }
    out[(long)b * HH + lane]      = acc1;
    out[(long)b * HH + 32 + lane] = acc2;
}

// ---------------- launch ----------------
extern "C" void kernel_launch(void* const* d_in, const int* in_sizes, int n_in,
                              void* d_out, int out_size)
{
    const int*   seq     = (const int*)  d_in[0];
    const float* embed_W = (const float*)d_in[1];
    const float* ff_w1   = (const float*)d_in[2];
    const float* ff_b1   = (const float*)d_in[3];
    const float* ff_w2   = (const float*)d_in[4];
    const float* ff_b2   = (const float*)d_in[5];
    const float* ln_g    = (const float*)d_in[6];
    const float* ln_b    = (const float*)d_in[7];
    const float* gate_w1 = (const float*)d_in[8];
    const float* gate_b1 = (const float*)d_in[9];
    const float* gate_w2 = (const float*)d_in[10];
    const float* gate_b2 = (const float*)d_in[11];
    const float* read_w  = (const float*)d_in[12];
    const float* read_b  = (const float*)d_in[13];
    const float* out_w   = (const float*)d_in[14];
    const float* out_b   = (const float*)d_in[15];

    prekA<<<HH, 128>>>(embed_W, ff_w1, ff_b1, ff_w2, ff_b2, ln_g, ln_b,
                       gate_w1, gate_b1, gate_w2, gate_b2);
    prekB<<<HH, HH>>>(read_w, read_b, out_w, out_b);
    prekC<<<HH, HH>>>();
    scan_kernel<<<BB / WPB, WPB * 32>>>(seq, (float*)d_out);
}

// round 6
// speedup vs baseline: 1.0155x; 1.0155x over previous
#include <cuda_runtime.h>
#include <math.h>

#define BB 2048
#define LL 1024
#define HH 64
#define VV 64
#define TT 16          // chunk length

// ---------------- precomputed tables ----------------
__device__ float d_K[HH * HH];
__device__ float d_g[HH];
__device__ float d_Gn[HH * HH];    // Gn[v][j] = -a_v * (k_v . k_j)
__device__ float d_r[HH];          // r_v = ||k_v||^2 + 1e-6
__device__ float d_Y[HH * HH];
__device__ float d_Z[HH * HH];
__device__ float d_bias2[HH];

// ---------------- precompute A ----------------
__global__ void __launch_bounds__(128) prekA(
    const float* __restrict__ embed_W, const float* __restrict__ ff_w1, const float* __restrict__ ff_b1,
    const float* __restrict__ ff_w2,   const float* __restrict__ ff_b2, const float* __restrict__ ln_g,
    const float* __restrict__ ln_b,    const float* __restrict__ gate_w1, const float* __restrict__ gate_b1,
    const float* __restrict__ gate_w2, const float* __restrict__ gate_b2)
{
    int v = blockIdx.x;
    int tid = threadIdx.x;
    __shared__ float se[HH];
    __shared__ float sz[2 * HH];
    __shared__ float sk[HH];
    __shared__ float sh[16];
    __shared__ float sred[4];

    if (tid < HH) se[tid] = embed_W[v * HH + tid];
    __syncthreads();

    {
        float z = ff_b1[tid];
        #pragma unroll 8
        for (int i = 0; i < HH; i++) z = fmaf(se[i], ff_w1[i * (2 * HH) + tid], z);
        sz[tid] = fmaxf(z, 0.0f);
    }
    __syncthreads();

    if (tid < HH) {
        float ff = ff_b2[tid];
        #pragma unroll 8
        for (int j = 0; j < 2 * HH; j++) ff = fmaf(sz[j], ff_w2[j * HH + tid], ff);
        float x = se[tid] + ff;

        float s = x;
        #pragma unroll
        for (int o = 16; o > 0; o >>= 1) s += __shfl_xor_sync(0xffffffffu, s, o);
        if ((tid & 31) == 0) sred[tid >> 5] = s;
        __syncwarp();
        __syncthreads();
        float mu = (sred[0] + sred[1]) * (1.0f / HH);

        float d = x - mu;
        float sv = d * d;
        #pragma unroll
        for (int o = 16; o > 0; o >>= 1) sv += __shfl_xor_sync(0xffffffffu, sv, o);
        if ((tid & 31) == 0) sred[2 + (tid >> 5)] = sv;
        __syncwarp();
        __syncthreads();
        float var = (sred[2] + sred[3]) * (1.0f / HH);
        float inv = rsqrtf(var + 1e-5f);
        float k = d * inv * ln_g[tid] + ln_b[tid];
        sk[tid] = k;
        d_K[v * HH + tid] = k;
    }
    __syncthreads();

    if (tid < 16) {
        float hj = gate_b1[tid];
        #pragma unroll 8
        for (int i = 0; i < HH; i++) hj = fmaf(sk[i], gate_w1[i * 16 + tid], hj);
        sh[tid] = fmaxf(hj, 0.0f);
    }
    __syncthreads();
    if (tid == 0) {
        float gz = gate_b2[0];
        #pragma unroll
        for (int j = 0; j < 16; j++) gz = fmaf(sh[j], gate_w2[j], gz);
        d_g[v] = 1.0f / (1.0f + expf(-gz));
    }
}

// ---------------- precompute B ----------------
__global__ void __launch_bounds__(64) prekB(
    const float* __restrict__ read_w, const float* __restrict__ read_b,
    const float* __restrict__ out_w,  const float* __restrict__ out_b)
{
    int v = blockIdx.x;
    int u = threadIdx.x;
    __shared__ float skv[HH];
    __shared__ float sdiag;

    skv[u] = d_K[v * HH + u];
    __syncthreads();

    float s = 0.0f;
    #pragma unroll 8
    for (int i = 0; i < HH; i++) s = fmaf(skv[i], d_K[u * HH + i], s);
    if (u == v) sdiag = s;
    __syncthreads();

    float denom = sdiag + 1e-6f;
    float a = d_g[v] / denom;
    d_Gn[v * HH + u] = -a * s;
    if (u == v) d_r[v] = denom;

    float y = 0.0f;
    #pragma unroll 8
    for (int m = 0; m < HH; m++) y = fmaf(read_w[v * HH + m], out_w[m * HH + u], y);
    d_Y[v * HH + u] = y;

    if (v == 0) {
        float b = out_b[u];
        #pragma unroll 8
        for (int m = 0; m < HH; m++) b = fmaf(read_b[m], out_w[m * HH + u], b);
        d_bias2[u] = b;
    }
}

// ---------------- precompute C ----------------
__global__ void __launch_bounds__(64) prekC()
{
    int v = blockIdx.x;
    int n = threadIdx.x;
    __shared__ float skv[HH];
    skv[n] = d_K[v * HH + n];
    __syncthreads();
    float s = 0.0f;
    #pragma unroll 8
    for (int h = 0; h < HH; h++) s = fmaf(skv[h], d_Y[h * HH + n], s);
    d_Z[v * HH + n] = s;
}

// ---------------- packed dual-fp32 helpers ----------------
__device__ __forceinline__ unsigned long long fma_f32x2(unsigned long long a, unsigned long long b,
                                                        unsigned long long c) {
    unsigned long long d;
    asm("fma.rn.f32x2 %0, %1, %2, %3;" : "=l"(d) : "l"(a), "l"(b), "l"(c));
    return d;
}
__device__ __forceinline__ unsigned long long bcast2(float x) {
    unsigned long long r;
    unsigned int u = __float_as_uint(x);
    asm("mov.b64 %0, {%1, %2};" : "=l"(r) : "r"(u), "r"(u));
    return r;
}
__device__ __forceinline__ void pairbar(int id) {
    asm volatile("bar.sync %0, %1;" :: "r"(id), "r"(64) : "memory");
}

// ---------------- scan: chunked delta rule, warp-PAIR per batch ----------------
// Warp wslot of a pair owns columns [wslot*32, wslot*32+32); lane owns ONE column
// (mycol = wslot*32 + lane) stored as 32 u64 (row pairs) in registers.
__global__ void __launch_bounds__(128, 4) scan_kernel(const int* __restrict__ seq, float* __restrict__ out)
{
    __shared__ float sGn[HH * HH];
    __shared__ float sr[HH];
    __shared__ __align__(16) float sS[2][2][TT][HH];   // [pair][buf][t][component]
    __shared__ float sC[2][TT][TT];

    int tid = threadIdx.x;
    #pragma unroll 1
    for (int i = tid; i < HH * HH; i += 128) sGn[i] = d_Gn[i];
    if (tid < HH) sr[tid] = d_r[tid];
    __syncthreads();

    int warp = tid >> 5, lane = tid & 31;
    int pair = warp >> 1, wslot = warp & 1;
    int b = blockIdx.x * 2 + pair;
    const int* seqb = seq + (long)b * LL;
    int mycol = wslot * 32 + lane;
    int barid = 1 + pair;
    float* Cm = &sC[pair][0][0];

    unsigned long long cP[32];
    #pragma unroll
    for (int i = 0; i < 32; i++) cP[i] = 0ull;

    const int nsteps = LL - 1;   // 1023
    int buf = 0;
    #pragma unroll 1
    for (int c0 = 0; c0 < nsteps; c0 += TT) {
        int T = nsteps - c0; if (T > TT) T = TT;
        int tokreg = (lane < T) ? seqb[c0 + lane] : 0;
        float* Sm = &sS[pair][buf][0][0];

        // ---- phase 1: owners dump needed columns of P0 into Sm rows (w_t) ----
        #pragma unroll 1
        for (int t = 0; t < T; t++) {
            int vt = __shfl_sync(0xffffffffu, tokreg, t);
            if ((vt >> 5) == wslot) {                 // warp-uniform branch
                if (lane == (vt & 31)) {
                    float* row = Sm + t * HH;
                    #pragma unroll
                    for (int p = 0; p < 32; p += 2) {
                        ulonglong2 t2; t2.x = cP[p]; t2.y = cP[p + 1];
                        *reinterpret_cast<ulonglong2*>(row + 2 * p) = t2;
                    }
                    row[vt] -= sr[vt];
                }
            }
        }

        // ---- build C[t][u] = Gn[v_u][v_t] (u < t); split t-range across the pair ----
        {
            int tlo = wslot ? 8 : 1;
            int thi = wslot ? T : (T < 8 ? T : 8);
            #pragma unroll 1
            for (int t = tlo; t < thi; t++) {
                int vt = __shfl_sync(0xffffffffu, tokreg, t);
                if (lane < t) Cm[t * TT + lane] = sGn[tokreg * HH + vt];
            }
        }
        pairbar(barid);

        // ---- phase 2: forward substitution, thread h handles component h ----
        {
            float sreg[TT];
            #pragma unroll
            for (int t = 0; t < TT; t++) {
                if (t < T) {
                    float acc = Sm[t * HH + mycol];
                    #pragma unroll
                    for (int u = 0; u < t; u++)
                        acc = fmaf(Cm[t * TT + u], sreg[u], acc);
                    sreg[t] = acc;
                    Sm[t * HH + mycol] = acc;
                }
            }
        }
        pairbar(barid);

        // ---- phase 3: P += sum_u s_u * gn_u^T (rank-T, branch/sync-free) ----
        #pragma unroll 2
        for (int u = 0; u < T; u++) {
            int vu = __shfl_sync(0xffffffffu, tokreg, u);
            unsigned long long cp = bcast2(sGn[vu * HH + mycol]);
            const ulonglong2* s2 = reinterpret_cast<const ulonglong2*>(Sm + u * HH);
            #pragma unroll
            for (int p = 0; p < 16; p++) {
                ulonglong2 sv = s2[p];
                cP[2 * p]     = fma_f32x2(cp, sv.x, cP[2 * p]);
                cP[2 * p + 1] = fma_f32x2(cp, sv.y, cP[2 * p + 1]);
            }
        }
        buf ^= 1;   // double buffer: next phase-1 writes the other Sm
    }

    // ---- final readout: logits = P[:,v_q]^T Z + bias2 ----
    int vq = seqb[LL - 1];
    float* sb = &sS[pair][0][0][0];   // last chunk (63) used buf=1; buf 0 free
    if ((vq >> 5) == wslot && lane == (vq & 31)) {
        #pragma unroll
        for (int p = 0; p < 32; p += 2) {
            ulonglong2 t2; t2.x = cP[p]; t2.y = cP[p + 1];
            *reinterpret_cast<ulonglong2*>(sb + 2 * p) = t2;
        }
    }
    pairbar(barid);

    float acc = d_bias2[mycol];
    #pragma unroll 8
    for (int i = 0; i < HH; i++)
        acc = fmaf(sb[i], d_Z[i * HH + mycol], acc);
    out[(long)b * HH + mycol] = acc;
}

// ---------------- launch ----------------
extern "C" void kernel_launch(void* const* d_in, const int* in_sizes, int n_in,
                              void* d_out, int out_size)
{
    const int*   seq     = (const int*)  d_in[0];
    const float* embed_W = (const float*)d_in[1];
    const float* ff_w1   = (const float*)d_in[2];
    const float* ff_b1   = (const float*)d_in[3];
    const float* ff_w2   = (const float*)d_in[4];
    const float* ff_b2   = (const float*)d_in[5];
    const float* ln_g    = (const float*)d_in[6];
    const float* ln_b    = (const float*)d_in[7];
    const float* gate_w1 = (const float*)d_in[8];
    const float* gate_b1 = (const float*)d_in[9];
    const float* gate_w2 = (const float*)d_in[10];
    const float* gate_b2 = (const float*)d_in[11];
    const float* read_w  = (const float*)d_in[12];
    const float* read_b  = (const float*)d_in[13];
    const float* out_w   = (const float*)d_in[14];
    const float* out_b   = (const float*)d_in[15];

    prekA<<<HH, 128>>>(embed_W, ff_w1, ff_b1, ff_w2, ff_b2, ln_g, ln_b,
                       gate_w1, gate_b1, gate_w2, gate_b2);
    prekB<<<HH, HH>>>(read_w, read_b, out_w, out_b);
    prekC<<<HH, HH>>>();
    scan_kernel<<<BB / 2, 128>>>(seq, (float*)d_out);
}

// round 9
// speedup vs baseline: 1.9375x; 1.9079x over previous
#include <cuda_runtime.h>
#include <math.h>
#include <stdint.h>

#define BB 2048
#define LL 1024
#define HH 64
#define TT 16
#define GSTR 72     // sGn row stride (floats): conflict-free B gathers, 16B-aligned rows
#define ASTR 20     // sA row stride (u32): conflict-free A fragment loads
#define PSTR 68     // sPT row stride (floats)

// ---------------- precomputed tables ----------------
__device__ float d_K[HH * HH];
__device__ float d_g[HH];
__device__ float d_Gn[HH * HH];    // Gn[v][j] = -a_v * (k_v . k_j)
__device__ float d_r[HH];          // r_v = ||k_v||^2 + 1e-6
__device__ float d_Y[HH * HH];
__device__ float d_Z[HH * HH];
__device__ float d_bias2[HH];

// ---------------- precompute A ----------------
__global__ void __launch_bounds__(128) prekA(
    const float* __restrict__ embed_W, const float* __restrict__ ff_w1, const float* __restrict__ ff_b1,
    const float* __restrict__ ff_w2,   const float* __restrict__ ff_b2, const float* __restrict__ ln_g,
    const float* __restrict__ ln_b,    const float* __restrict__ gate_w1, const float* __restrict__ gate_b1,
    const float* __restrict__ gate_w2, const float* __restrict__ gate_b2)
{
    int v = blockIdx.x;
    int tid = threadIdx.x;
    __shared__ float se[HH];
    __shared__ float sz[2 * HH];
    __shared__ float sk[HH];
    __shared__ float sh[16];
    __shared__ float sred[4];

    if (tid < HH) se[tid] = embed_W[v * HH + tid];
    __syncthreads();

    {
        float z = ff_b1[tid];
        #pragma unroll 8
        for (int i = 0; i < HH; i++) z = fmaf(se[i], ff_w1[i * (2 * HH) + tid], z);
        sz[tid] = fmaxf(z, 0.0f);
    }
    __syncthreads();

    if (tid < HH) {
        float ff = ff_b2[tid];
        #pragma unroll 8
        for (int j = 0; j < 2 * HH; j++) ff = fmaf(sz[j], ff_w2[j * HH + tid], ff);
        float x = se[tid] + ff;

        float s = x;
        #pragma unroll
        for (int o = 16; o > 0; o >>= 1) s += __shfl_xor_sync(0xffffffffu, s, o);
        if ((tid & 31) == 0) sred[tid >> 5] = s;
        __syncwarp();
        __syncthreads();
        float mu = (sred[0] + sred[1]) * (1.0f / HH);

        float d = x - mu;
        float sv = d * d;
        #pragma unroll
        for (int o = 16; o > 0; o >>= 1) sv += __shfl_xor_sync(0xffffffffu, sv, o);
        if ((tid & 31) == 0) sred[2 + (tid >> 5)] = sv;
        __syncwarp();
        __syncthreads();
        float var = (sred[2] + sred[3]) * (1.0f / HH);
        float inv = rsqrtf(var + 1e-5f);
        float k = d * inv * ln_g[tid] + ln_b[tid];
        sk[tid] = k;
        d_K[v * HH + tid] = k;
    }
    __syncthreads();

    if (tid < 16) {
        float hj = gate_b1[tid];
        #pragma unroll 8
        for (int i = 0; i < HH; i++) hj = fmaf(sk[i], gate_w1[i * 16 + tid], hj);
        sh[tid] = fmaxf(hj, 0.0f);
    }
    __syncthreads();
    if (tid == 0) {
        float gz = gate_b2[0];
        #pragma unroll
        for (int j = 0; j < 16; j++) gz = fmaf(sh[j], gate_w2[j], gz);
        d_g[v] = 1.0f / (1.0f + expf(-gz));
    }
}

// ---------------- precompute B ----------------
__global__ void __launch_bounds__(64) prekB(
    const float* __restrict__ read_w, const float* __restrict__ read_b,
    const float* __restrict__ out_w,  const float* __restrict__ out_b)
{
    int v = blockIdx.x;
    int u = threadIdx.x;
    __shared__ float skv[HH];
    __shared__ float sdiag;

    skv[u] = d_K[v * HH + u];
    __syncthreads();

    float s = 0.0f;
    #pragma unroll 8
    for (int i = 0; i < HH; i++) s = fmaf(skv[i], d_K[u * HH + i], s);
    if (u == v) sdiag = s;
    __syncthreads();

    float denom = sdiag + 1e-6f;
    float a = d_g[v] / denom;
    d_Gn[v * HH + u] = -a * s;
    if (u == v) d_r[v] = denom;

    float y = 0.0f;
    #pragma unroll 8
    for (int m = 0; m < HH; m++) y = fmaf(read_w[v * HH + m], out_w[m * HH + u], y);
    d_Y[v * HH + u] = y;

    if (v == 0) {
        float b = out_b[u];
        #pragma unroll 8
        for (int m = 0; m < HH; m++) b = fmaf(read_b[m], out_w[m * HH + u], b);
        d_bias2[u] = b;
    }
}

// ---------------- precompute C ----------------
__global__ void __launch_bounds__(64) prekC()
{
    int v = blockIdx.x;
    int n = threadIdx.x;
    __shared__ float skv[HH];
    skv[n] = d_K[v * HH + n];
    __syncthreads();
    float s = 0.0f;
    #pragma unroll 8
    for (int h = 0; h < HH; h++) s = fmaf(skv[h], d_Y[h * HH + n], s);
    d_Z[v * HH + n] = s;
}

// ---------------- mma helpers (baseline PTX, sm_80+) ----------------
__device__ __forceinline__ uint32_t tf32b(float x) {
    uint32_t r;
    asm("cvt.rna.tf32.f32 %0, %1;" : "=r"(r) : "f"(x));
    return r;
}
__device__ __forceinline__ void mma8(float* c,
                                     uint32_t a0, uint32_t a1, uint32_t a2, uint32_t a3,
                                     uint32_t b0, uint32_t b1) {
    asm("mma.sync.aligned.m16n8k8.row.col.f32.tf32.tf32.f32 "
        "{%0,%1,%2,%3},{%4,%5,%6,%7},{%8,%9},{%0,%1,%2,%3};"
        : "+f"(c[0]), "+f"(c[1]), "+f"(c[2]), "+f"(c[3])
        : "r"(a0), "r"(a1), "r"(a2), "r"(a3), "r"(b0), "r"(b1));
}

// ---------------- scan: chunked delta rule, P in mma register fragments ----------------
// One CTA = one batch. Warp w owns P rows [16w, 16w+16), all 8 n-tiles of 8 cols.
// Per chunk: dump P^T -> smem, solve 16-step triangular system (warps 0-1),
// stage S split hi/lo (3xTF32), then 48 mma.sync rank-16 update per warp.
__global__ void __launch_bounds__(128) scan_mma(const int* __restrict__ seq, float* __restrict__ out)
{
    __shared__ float sGn[HH * GSTR];                       // fp32 Gn (padded rows)
    __shared__ __align__(16) uint32_t sAhi[HH * ASTR];     // S^T hi (tf32 bits), row h, col u
    __shared__ __align__(16) uint32_t sAlo[HH * ASTR];     // S^T lo
    __shared__ float sPT[HH * PSTR];                       // P transposed: row = col-of-P
    __shared__ float sC[TT * TT];                          // triangular coeffs
    __shared__ float sr[HH];
    __shared__ int   stok[2][TT];

    int tid = threadIdx.x;
    int warp = tid >> 5, lane = tid & 31;
    int gid = lane >> 2, tig = lane & 3;
    int m0 = warp * 16;
    long b = blockIdx.x;
    const int* seqb = seq + b * LL;

    #pragma unroll 1
    for (int i = tid; i < HH * HH; i += 128) {
        int r = i >> 6, cc = i & 63;
        sGn[r * GSTR + cc] = d_Gn[i];
    }
    if (tid < HH) sr[tid] = d_r[tid];

    float Cacc[8][4];
    #pragma unroll
    for (int nt = 0; nt < 8; nt++)
        #pragma unroll
        for (int q = 0; q < 4; q++) Cacc[nt][q] = 0.0f;

    const int nsteps = LL - 1;   // 1023
    const int NCH = (nsteps + TT - 1) / TT;  // 64

    int ntok = (tid < TT) ? ((tid < nsteps) ? seqb[tid] : 0) : 0;
    __syncthreads();

    #pragma unroll 1
    for (int c = 0; c < NCH; c++) {
        int c0 = c * TT;
        int cb = c & 1;

        // P1: publish this chunk's tokens; prefetch next chunk's
        if (tid < TT) {
            stok[cb][tid] = ntok;
            int p = c0 + TT + tid;
            ntok = (p < nsteps) ? seqb[p] : 0;
        }
        __syncthreads();   // BAR 1: tokens visible; prev chunk fully retired

        // P3a: dump P (pre-update) transposed to sPT. Conflict-free STS.32.
        #pragma unroll
        for (int nt = 0; nt < 8; nt++) {
            int r0 = m0 + gid, r1 = r0 + 8;
            int cA = nt * 8 + tig * 2, cB = cA + 1;
            sPT[cA * PSTR + r0] = Cacc[nt][0];
            sPT[cB * PSTR + r0] = Cacc[nt][1];
            sPT[cA * PSTR + r1] = Cacc[nt][2];
            sPT[cB * PSTR + r1] = Cacc[nt][3];
        }
        // P3b: warps 2-3 build C[t][u] = Gn[v_u][v_t] (u < t), 120 entries
        if (warp >= 2) {
            int j = tid - 64;
            #pragma unroll 1
            for (int e = j; e < 120; e += 64) {
                float tf = floorf((1.0f + sqrtf(1.0f + 8.0f * (float)e)) * 0.5f);
                int t = (int)tf;
                int u = e - (t * (t - 1)) / 2;
                sC[t * TT + u] = sGn[stok[cb][u] * GSTR + stok[cb][t]];
            }
        }
        __syncthreads();   // BAR 2: sPT + sC ready

        // P4: warps 0-1 solve; thread h handles component h.
        if (warp < 2) {
            int h = tid;
            float s[TT];
            float rh = sr[h];
            #pragma unroll
            for (int t = 0; t < TT; t++) {
                int vt = stok[cb][t];
                float acc = sPT[vt * PSTR + h];
                if (vt == h) acc -= rh;
                #pragma unroll
                for (int u = 0; u < TT; u++)
                    if (u < t) acc = fmaf(sC[t * TT + u], s[u], acc);
                if (c0 + t >= nsteps) acc = 0.0f;   // pad steps contribute nothing
                s[t] = acc;
            }
            // split 3xTF32 and stage A = S^T (row h = component, cols u)
            uint32_t hb[TT], lb[TT];
            #pragma unroll
            for (int t = 0; t < TT; t++) {
                uint32_t hbits = tf32b(s[t]);
                hb[t] = hbits;
                lb[t] = tf32b(s[t] - __uint_as_float(hbits));
            }
            uint4* ph = (uint4*)&sAhi[h * ASTR];
            uint4* pl = (uint4*)&sAlo[h * ASTR];
            #pragma unroll
            for (int q = 0; q < 4; q++) {
                ph[q] = make_uint4(hb[4*q], hb[4*q+1], hb[4*q+2], hb[4*q+3]);
                pl[q] = make_uint4(lb[4*q], lb[4*q+1], lb[4*q+2], lb[4*q+3]);
            }
        }
        __syncthreads();   // BAR 3: A staged

        // P5: rank-16 update via mma.sync (2 k-steps x 8 n-tiles x 3 products)
        #pragma unroll
        for (int kx = 0; kx < 2; kx++) {
            int k0 = kx * 8;
            int u0 = k0 + tig, u4 = u0 + 4;
            int t0 = stok[cb][u0];
            int t4 = stok[cb][u4];
            uint32_t ah0 = sAhi[(m0 + gid)     * ASTR + u0];
            uint32_t ah1 = sAhi[(m0 + gid + 8) * ASTR + u0];
            uint32_t ah2 = sAhi[(m0 + gid)     * ASTR + u4];
            uint32_t ah3 = sAhi[(m0 + gid + 8) * ASTR + u4];
            uint32_t al0 = sAlo[(m0 + gid)     * ASTR + u0];
            uint32_t al1 = sAlo[(m0 + gid + 8) * ASTR + u0];
            uint32_t al2 = sAlo[(m0 + gid)     * ASTR + u4];
            uint32_t al3 = sAlo[(m0 + gid + 8) * ASTR + u4];
            #pragma unroll
            for (int nt = 0; nt < 8; nt++) {
                int n = nt * 8 + gid;
                float g0 = sGn[t0 * GSTR + n];
                float g4 = sGn[t4 * GSTR + n];
                uint32_t bh0 = tf32b(g0), bh1 = tf32b(g4);
                uint32_t bl0 = tf32b(g0 - __uint_as_float(bh0));
                uint32_t bl1 = tf32b(g4 - __uint_as_float(bh1));
                mma8(Cacc[nt], ah0, ah1, ah2, ah3, bh0, bh1);   // hi*hi
                mma8(Cacc[nt], ah0, ah1, ah2, ah3, bl0, bl1);   // hi*lo
                mma8(Cacc[nt], al0, al1, al2, al3, bh0, bh1);   // lo*hi
            }
        }
    }

    // ---- final: dump P once more, read column v_q, logits = P[:,vq]^T Z + bias2 ----
    __syncthreads();
    #pragma unroll
    for (int nt = 0; nt < 8; nt++) {
        int r0 = m0 + gid, r1 = r0 + 8;
        int cA = nt * 8 + tig * 2, cB = cA + 1;
        sPT[cA * PSTR + r0] = Cacc[nt][0];
        sPT[cB * PSTR + r0] = Cacc[nt][1];
        sPT[cA * PSTR + r1] = Cacc[nt][2];
        sPT[cB * PSTR + r1] = Cacc[nt][3];
    }
    __syncthreads();

    if (tid < HH) {
        int n = tid;
        int vq = seqb[LL - 1];
        const float* pcol = &sPT[vq * PSTR];
        float acc = d_bias2[n];
        #pragma unroll 8
        for (int i = 0; i < HH; i++)
            acc = fmaf(pcol[i], d_Z[i * HH + n], acc);
        out[b * HH + n] = acc;
    }
}

// ---------------- launch ----------------
extern "C" void kernel_launch(void* const* d_in, const int* in_sizes, int n_in,
                              void* d_out, int out_size)
{
    const int*   seq     = (const int*)  d_in[0];
    const float* embed_W = (const float*)d_in[1];
    const float* ff_w1   = (const float*)d_in[2];
    const float* ff_b1   = (const float*)d_in[3];
    const float* ff_w2   = (const float*)d_in[4];
    const float* ff_b2   = (const float*)d_in[5];
    const float* ln_g    = (const float*)d_in[6];
    const float* ln_b    = (const float*)d_in[7];
    const float* gate_w1 = (const float*)d_in[8];
    const float* gate_b1 = (const float*)d_in[9];
    const float* gate_w2 = (const float*)d_in[10];
    const float* gate_b2 = (const float*)d_in[11];
    const float* read_w  = (const float*)d_in[12];
    const float* read_b  = (const float*)d_in[13];
    const float* out_w   = (const float*)d_in[14];
    const float* out_b   = (const float*)d_in[15];

    prekA<<<HH, 128>>>(embed_W, ff_w1, ff_b1, ff_w2, ff_b2, ln_g, ln_b,
                       gate_w1, gate_b1, gate_w2, gate_b2);
    prekB<<<HH, HH>>>(read_w, read_b, out_w, out_b);
    prekC<<<HH, HH>>>();
    scan_mma<<<BB, 128>>>(seq, (float*)d_out);
}